// round 6
// baseline (speedup 1.0000x reference)
#include <cuda_runtime.h>
#include <cuda_bf16.h>
#include <cfloat>

// SpatialAttentionModule: x[16,64,256,256] f32
//   avg = mean_c(x), mx = max_c(x); mask = sigmoid(conv7x7_2to1([avg;mx]) + b)
//   out = x * mask
//
// K1 reduce: channel mean/max -> g_avg/g_max (8 MB, L2-resident). MLP 16.
// K2 fuse:   block = (b, 4-row group). Conv+sigmoid for 4 rows in SMEM
//            (prologue amortized 4x vs 1-row blocks), then stream
//            4 rows x 64 ch with the (q, csub) pattern that measured best.

#define B_  16
#define C_  64
#define H_  256
#define W_  256
#define HW  (H_ * W_)
#define HW4 (HW / 4)               // float4 per (b,c) plane
#define KS  7
#define PADK 3
#define WPAD (W_ + 2 * PADK)       // 262
#define RG  4                      // rows per block
#define HALO (RG + KS - 1)         // 10 staged rows per input channel

__device__ float g_avg[B_ * HW];
__device__ float g_max[B_ * HW];

__global__ __launch_bounds__(256) void reduce_kernel(const float4* __restrict__ x) {
    int g  = blockIdx.x * 256 + threadIdx.x;
    int b  = g >> 14;
    int hw = g & (HW4 - 1);

    const float4* p = x + ((size_t)b * C_) * HW4 + hw;

    float4 s = make_float4(0.f, 0.f, 0.f, 0.f);
    float4 m = make_float4(-FLT_MAX, -FLT_MAX, -FLT_MAX, -FLT_MAX);

    #pragma unroll 16
    for (int c = 0; c < C_; ++c) {
        float4 v = __ldcs(p + (size_t)c * HW4);
        s.x += v.x; s.y += v.y; s.z += v.z; s.w += v.w;
        m.x = fmaxf(m.x, v.x); m.y = fmaxf(m.y, v.y);
        m.z = fmaxf(m.z, v.z); m.w = fmaxf(m.w, v.w);
    }

    const float inv = 1.0f / (float)C_;
    float4 a = make_float4(s.x * inv, s.y * inv, s.z * inv, s.w * inv);
    reinterpret_cast<float4*>(g_avg)[g] = a;   // default policy: keep in L2
    reinterpret_cast<float4*>(g_max)[g] = m;
}

__global__ __launch_bounds__(256) void fuse_kernel(const float* __restrict__ x,
                                                   const float* __restrict__ conv_w,
                                                   const float* __restrict__ conv_b,
                                                   float* __restrict__ out) {
    __shared__ float sw[2 * KS * KS];                    // 98 weights
    __shared__ float sm[2 * HALO * WPAD];                // 10 halo rows x 2 ch, padded
    __shared__ __align__(16) float smask[RG][W_];        // masks for the 4 rows

    const int tid = threadIdx.x;
    const int b   = blockIdx.x >> 6;                     // 64 row-groups per batch
    const int h0  = (blockIdx.x & 63) * RG;              // first output row

    if (tid < 2 * KS * KS) sw[tid] = __ldg(&conv_w[tid]);

    // Stage padded halo rows: sm[(ic*HALO+rr)*WPAD + wp], global row = h0-3+rr.
    for (int i = tid; i < 2 * HALO * WPAD; i += 256) {
        int ic = i / (HALO * WPAD);
        int r  = i - ic * (HALO * WPAD);
        int rr = r / WPAD;
        int wp = r - rr * WPAD;
        int wc = wp - PADK;
        int hh = h0 - PADK + rr;
        float v = 0.f;
        if (hh >= 0 && hh < H_ && wc >= 0 && wc < W_) {
            const float* plane = ic ? g_max : g_avg;
            v = __ldg(&plane[((size_t)b * H_ + hh) * W_ + wc]);   // L2 hit
        }
        sm[i] = v;
    }
    __syncthreads();

    // Conv+sigmoid: each thread computes RG pixels (one per row), col = tid.
    {
        const float bias = __ldg(&conv_b[0]);
        #pragma unroll
        for (int rs = 0; rs < RG; ++rs) {
            float acc = bias;
            #pragma unroll
            for (int ic = 0; ic < 2; ++ic) {
                #pragma unroll
                for (int kh = 0; kh < KS; ++kh) {
                    const float* row = &sm[(ic * HALO + rs + kh) * WPAD + tid];
                    const float* wr  = &sw[(ic * KS + kh) * KS];
                    #pragma unroll
                    for (int kw = 0; kw < KS; ++kw)
                        acc += row[kw] * wr[kw];
                }
            }
            smask[rs][tid] = 1.0f / (1.0f + __expf(-acc));
        }
    }
    __syncthreads();

    // Stream: 256 threads = 4 channels x 64 float4-columns.
    const int q    = tid & 63;
    const int csub = tid >> 6;
    const float4* x4 = reinterpret_cast<const float4*>(x);
    float4*       o4 = reinterpret_cast<float4*>(out);

    #pragma unroll
    for (int rs = 0; rs < RG; ++rs) {
        const float4 mk = reinterpret_cast<const float4*>(smask[rs])[q];
        size_t base = (((size_t)b * C_) * H_ + (h0 + rs)) * (W_ / 4) + q;
        #pragma unroll 4
        for (int cg = 0; cg < C_ / 4; ++cg) {
            int c = cg * 4 + csub;
            size_t idx = base + (size_t)c * HW4;
            float4 v = __ldcs(&x4[idx]);
            v.x *= mk.x; v.y *= mk.y; v.z *= mk.z; v.w *= mk.w;
            __stcs(&o4[idx], v);
        }
    }
}

extern "C" void kernel_launch(void* const* d_in, const int* in_sizes, int n_in,
                              void* d_out, int out_size) {
    const float* x      = (const float*)d_in[0];
    const float* conv_w = (const float*)d_in[1];
    const float* conv_b = (const float*)d_in[2];
    float* out          = (float*)d_out;

    reduce_kernel<<<(B_ * HW4) / 256, 256>>>((const float4*)x);
    fuse_kernel<<<B_ * (H_ / RG), 256>>>(x, conv_w, conv_b, out);
}

// round 7
// speedup vs baseline: 2.0466x; 2.0466x over previous
#include <cuda_runtime.h>
#include <cuda_bf16.h>
#include <cfloat>

// SpatialAttentionModule: x[16,64,256,256] f32
//   avg = mean_c(x), mx = max_c(x); mask = sigmoid(conv7x7_2to1([avg;mx]) + b)
//   out = x * mask
//
// K1 reduce: channel mean/max -> g_avg/g_max (8 MB, L2-resident). unroll 16 (44.4us measured).
// K2 fuse:   block = (b, 2-row group). Conv+sigmoid in SMEM then stream 2 rows x 64 ch.
//            HARD register cap via __launch_bounds__(256,8) + unroll-1 row loops:
//            R6 showed full RG unrolling -> 200 regs -> occ 12% -> 3x slowdown.

#define B_  16
#define C_  64
#define H_  256
#define W_  256
#define HW  (H_ * W_)
#define HW4 (HW / 4)               // float4 per (b,c) plane
#define KS  7
#define PADK 3
#define WPAD (W_ + 2 * PADK)       // 262
#define RG  2                      // rows per block
#define HALO (RG + KS - 1)         // 8 staged rows per input channel

__device__ float g_avg[B_ * HW];
__device__ float g_max[B_ * HW];

__global__ __launch_bounds__(256) void reduce_kernel(const float4* __restrict__ x) {
    int g  = blockIdx.x * 256 + threadIdx.x;
    int b  = g >> 14;
    int hw = g & (HW4 - 1);

    const float4* p = x + ((size_t)b * C_) * HW4 + hw;

    float4 s = make_float4(0.f, 0.f, 0.f, 0.f);
    float4 m = make_float4(-FLT_MAX, -FLT_MAX, -FLT_MAX, -FLT_MAX);

    #pragma unroll 16
    for (int c = 0; c < C_; ++c) {
        float4 v = __ldcs(p + (size_t)c * HW4);
        s.x += v.x; s.y += v.y; s.z += v.z; s.w += v.w;
        m.x = fmaxf(m.x, v.x); m.y = fmaxf(m.y, v.y);
        m.z = fmaxf(m.z, v.z); m.w = fmaxf(m.w, v.w);
    }

    const float inv = 1.0f / (float)C_;
    float4 a = make_float4(s.x * inv, s.y * inv, s.z * inv, s.w * inv);
    reinterpret_cast<float4*>(g_avg)[g] = a;   // default policy: keep in L2
    reinterpret_cast<float4*>(g_max)[g] = m;
}

// min 8 blocks/SM -> ptxas register cap 32: protects occupancy (R6 lesson).
__global__ __launch_bounds__(256, 8) void fuse_kernel(const float* __restrict__ x,
                                                      const float* __restrict__ conv_w,
                                                      const float* __restrict__ conv_b,
                                                      float* __restrict__ out) {
    __shared__ float sw[2 * KS * KS];                    // 98 weights
    __shared__ float sm[2 * HALO * WPAD];                // 8 halo rows x 2 ch, padded
    __shared__ __align__(16) float smask[RG][W_];        // masks for the RG rows

    const int tid = threadIdx.x;
    const int b   = blockIdx.x >> 7;                     // 128 row-groups per batch
    const int h0  = (blockIdx.x & 127) * RG;             // first output row

    if (tid < 2 * KS * KS) sw[tid] = __ldg(&conv_w[tid]);

    // Stage padded halo rows: sm[(ic*HALO+rr)*WPAD + wp], global row = h0-3+rr.
    for (int i = tid; i < 2 * HALO * WPAD; i += 256) {
        int ic = i / (HALO * WPAD);
        int r  = i - ic * (HALO * WPAD);
        int rr = r / WPAD;
        int wp = r - rr * WPAD;
        int wc = wp - PADK;
        int hh = h0 - PADK + rr;
        float v = 0.f;
        if (hh >= 0 && hh < H_ && wc >= 0 && wc < W_) {
            const float* plane = ic ? g_max : g_avg;
            v = __ldg(&plane[((size_t)b * H_ + hh) * W_ + wc]);   // L2 hit
        }
        sm[i] = v;
    }
    __syncthreads();

    // Conv+sigmoid: one pipeline, reused per row (unroll 1 keeps regs low).
    {
        const float bias = __ldg(&conv_b[0]);
        #pragma unroll 1
        for (int rs = 0; rs < RG; ++rs) {
            float acc = bias;
            #pragma unroll
            for (int ic = 0; ic < 2; ++ic) {
                #pragma unroll
                for (int kh = 0; kh < KS; ++kh) {
                    const float* row = &sm[(ic * HALO + rs + kh) * WPAD + tid];
                    const float* wr  = &sw[(ic * KS + kh) * KS];
                    #pragma unroll
                    for (int kw = 0; kw < KS; ++kw)
                        acc += row[kw] * wr[kw];
                }
            }
            smask[rs][tid] = 1.0f / (1.0f + __expf(-acc));
        }
    }
    __syncthreads();

    // Stream: 256 threads = 4 channels x 64 float4-columns. One row at a time.
    const int q    = tid & 63;
    const int csub = tid >> 6;
    const float4* x4 = reinterpret_cast<const float4*>(x);
    float4*       o4 = reinterpret_cast<float4*>(out);

    #pragma unroll 1
    for (int rs = 0; rs < RG; ++rs) {
        const float4 mk = reinterpret_cast<const float4*>(smask[rs])[q];
        size_t base = (((size_t)b * C_) * H_ + (h0 + rs)) * (W_ / 4) + q;
        #pragma unroll 4
        for (int cg = 0; cg < C_ / 4; ++cg) {
            int c = cg * 4 + csub;
            size_t idx = base + (size_t)c * HW4;
            float4 v = __ldcs(&x4[idx]);
            v.x *= mk.x; v.y *= mk.y; v.z *= mk.z; v.w *= mk.w;
            __stcs(&o4[idx], v);
        }
    }
}

extern "C" void kernel_launch(void* const* d_in, const int* in_sizes, int n_in,
                              void* d_out, int out_size) {
    const float* x      = (const float*)d_in[0];
    const float* conv_w = (const float*)d_in[1];
    const float* conv_b = (const float*)d_in[2];
    float* out          = (float*)d_out;

    reduce_kernel<<<(B_ * HW4) / 256, 256>>>((const float4*)x);
    fuse_kernel<<<B_ * (H_ / RG), 256>>>(x, conv_w, conv_b, out);
}